// round 4
// baseline (speedup 1.0000x reference)
#include <cuda_runtime.h>

#define DIMS   120
#define NPIX   14400        // 120*120
#define SS2    81
#define C32    32
#define B64    64
#define PITCH  84           // 81 padded to 84 floats; cols 81..83 zeroed
#define V4PIX  841          // 29*29
#define FLATN  13456        // 16*841
#define PAIRS  5            // pixel-pairs per v1 block (10 pixels, same image row)

// Intermediates (allocation-free scratch)
__device__ float g_cplx[8 * NPIX * B64];   // [s][pix][b]
__device__ float g_v4[B64 * FLATN];        // [b][o*841 + pix]

typedef unsigned long long ull;

__device__ __forceinline__ void fma_x2(ull& d, ull a, ull b) {
    asm("fma.rn.f32x2 %0, %1, %2, %0;" : "+l"(d) : "l"(a), "l"(b));
}
__device__ __forceinline__ float hsum_x2(ull v) {
    float2 f = *reinterpret_cast<float2*>(&v);
    return f.x + f.y;
}
__device__ __forceinline__ void cp_async4(void* smem_dst, const void* gmem_src) {
    unsigned s = (unsigned)__cvta_generic_to_shared(smem_dst);
    asm volatile("cp.async.ca.shared.global [%0], [%1], 4;" :: "r"(s), "l"(gmem_src));
}

// smem layout (floats): w[2 buf][2 pix][32 rows][84] then p[2 pix][64][84]
#define W_OFF(buf, pix) ((((buf) * 2 + (pix)) * 32) * PITCH)
#define P_OFF(pix)      ((128 + (pix) * 64) * PITCH)
#define SMEM_FLOATS     (256 * PITCH)          // 21504 floats = 86016 B

// ---------------------------------------------------------------------------
// V1: per-pixel 64x32x81 GEMM + relu + phase-mean. Block = 128 threads =
// 2 pixels x 64 threads, tile 8 batches x 4 channels per thread (f32x2 over
// even/odd k). Weights double-buffered with cp.async, warp-per-channel
// staging (fully coalesced, constant offsets). Carry-based patch staging.
// ---------------------------------------------------------------------------
__global__ __launch_bounds__(128)
void v1_kernel(const float* __restrict__ x, const float* __restrict__ w)
{
    extern __shared__ __align__(16) float sm[];
    int t = threadIdx.x;

    int row_i = blockIdx.x / 12;            // image row
    int j0    = (blockIdx.x % 12) * 10;     // first column of the 10 pixels
    int p0base = row_i * DIMS + j0;

    // zero the k-padding (cols 81..83) of all 256 rows, once
    for (int rr = t; rr < 256; rr += 128) {
        sm[rr * PITCH + 81] = 0.f;
        sm[rr * PITCH + 82] = 0.f;
        sm[rr * PITCH + 83] = 0.f;
    }

    int lane = t & 31;
    int wrp  = t >> 5;
    bool l3  = lane < 17;      // third 32-chunk covers k=64..80

    // ---- weight prefetch for pair (p0,p0+1) into buffer buf ----
    auto prefetch = [&](int p0, int buf) {
#pragma unroll
        for (int g = 0; g < 16; g++) {
            int cs  = wrp + 4 * g;          // channel slot 0..63
            int pix = cs >> 5;
            int c   = cs & 31;
            int rowp = (c >> 2) + ((c & 3) << 3);
            const float* src = w + (c * NPIX + (p0 + pix)) * SS2 + lane;
            float* dst = &sm[W_OFF(buf, pix) + rowp * PITCH + lane];
            cp_async4(dst, src);
            cp_async4(dst + 32, src + 32);
            if (l3) cp_async4(dst + 64, src + 64);
        }
        asm volatile("cp.async.commit_group;");
    };

    prefetch(p0base, 0);

    int u   = t & 63;          // thread within pixel-half
    int pix = t >> 6;
    int tx  = u & 7;           // orientation (channel quad via permuted rows)
    int ty  = u >> 3;          // batch sub-index 0..7

    for (int n = 0; n < PAIRS; n++) {
        int p0  = p0base + 2 * n;
        int buf = n & 1;

        // ---- stage patches for both pixels (carry-based indices, coalesced) ----
#pragma unroll
        for (int px = 0; px < 2; px++) {
            const float* xb = x + row_i * 128 + (j0 + 2 * n + px);
            float* ps = &sm[P_OFF(px)];
            int b = t / SS2;               // 0 or 1
            int k = t - b * SS2;
            int r = k / 9;
            int q = k - r * 9;
            for (int it = 0; it < 40; it++) {
                ps[b * PITCH + k] = xb[(b << 14) + (r << 7) + q];
                k += 47;
                int kc = (k >= SS2);
                k -= kc ? SS2 : 0;
                b += 1 + kc;
                r += kc ? -4 : 5;
                q += 2;
                if (q >= 9) { q -= 9; r += 1; }
            }
            if (t < 64) {                   // tail element 5120 + t
                ps[b * PITCH + k] = xb[(b << 14) + (r << 7) + q];
            }
        }

        // ---- prefetch next pair ----
        if (n + 1 < PAIRS) {
            prefetch(p0base + 2 * (n + 1), buf ^ 1);
            asm volatile("cp.async.wait_group 1;");
        } else {
            asm volatile("cp.async.wait_group 0;");
        }
        __syncthreads();

        // ---- GEMM: 8b x 4c per thread, f32x2 over (k even, k odd) ----
        const float* wb = &sm[W_OFF(buf, pix)];
        const float* pb = &sm[P_OFF(pix)];

        ull acc[8][4];
#pragma unroll
        for (int bi = 0; bi < 8; bi++)
#pragma unroll
            for (int ci = 0; ci < 4; ci++) acc[bi][ci] = 0ull;

#pragma unroll 3
        for (int kq = 0; kq < 21; kq++) {
            ulonglong2 wv[4];
#pragma unroll
            for (int ci = 0; ci < 4; ci++)
                wv[ci] = *(const ulonglong2*)&wb[(tx + (ci << 3)) * PITCH + kq * 4];
#pragma unroll
            for (int bi = 0; bi < 8; bi++) {
                ulonglong2 pv = *(const ulonglong2*)&pb[(ty + (bi << 3)) * PITCH + kq * 4];
#pragma unroll
                for (int ci = 0; ci < 4; ci++) {
                    fma_x2(acc[bi][ci], pv.x, wv[ci].x);
                    fma_x2(acc[bi][ci], pv.y, wv[ci].y);
                }
            }
        }
        __syncthreads();   // all reads of w_s[buf] / p_s done

        // ---- relu + phase-mean -> bounce in retired weight buffer ----
        float* bounce = &sm[W_OFF(buf, pix)];
#pragma unroll
        for (int bi = 0; bi < 8; bi++) {
            float s0 = fmaxf(hsum_x2(acc[bi][0]), 0.f);
            float s1 = fmaxf(hsum_x2(acc[bi][1]), 0.f);
            float s2 = fmaxf(hsum_x2(acc[bi][2]), 0.f);
            float s3 = fmaxf(hsum_x2(acc[bi][3]), 0.f);
            bounce[tx * PITCH + ty + (bi << 3)] = (s0 + s1 + s2 + s3) * 0.25f;
        }
        __syncthreads();

        // ---- coalesced store: 2 pixels x 8 orient x 64 batch ----
        {
            int s2i = u >> 3;               // orientation 0..7
            int b16 = (u & 7) << 3;         // batch offset 0..56 step 8
            const float* src = &sm[W_OFF(buf, pix) + s2i * PITCH + b16];
            float4 v0 = *(const float4*)&src[0];
            float4 v1 = *(const float4*)&src[4];
            float* dst = &g_cplx[(s2i * NPIX + (p0 + pix)) * B64 + b16];
            *(float4*)&dst[0] = v0;
            *(float4*)&dst[4] = v1;
        }
        __syncthreads();   // protect bounce region from next cp.async overwrite
    }
}

// ---------------------------------------------------------------------------
// V4 locally-connected pooling. One block per V4 pixel.
// ---------------------------------------------------------------------------
__global__ __launch_bounds__(128, 8)
void v4_kernel(const float* __restrict__ vw)
{
    int p = blockIdx.x;                 // 0..840
    int ii = p / 29;
    int jj = p - ii * 29;
    int base_pix = (ii * 4) * DIMS + jj * 4;

    __shared__ __align__(16) float w_s[64][32];   // [k][o duplicated x2]
    __shared__ __align__(16) float p_s[64][64];   // [pos][b]

    int t = threadIdx.x;
    int to = t & 7;
    int tb = t >> 3;
    int o0 = to * 2;
    int b0 = tb * 4;

    ull acc[2][2];
    acc[0][0] = acc[0][1] = acc[1][0] = acc[1][1] = 0ull;

    for (int s = 0; s < 8; s++) {
        __syncthreads();
        for (int f = t; f < 256; f += 128) {
            int o = f >> 4, kq = f & 15;
            float4 v = *(const float4*)&vw[((((o << 3) + s) * V4PIX) + p) * 64 + kq * 4];
            *(float2*)&w_s[kq * 4 + 0][o * 2] = make_float2(v.x, v.x);
            *(float2*)&w_s[kq * 4 + 1][o * 2] = make_float2(v.y, v.y);
            *(float2*)&w_s[kq * 4 + 2][o * 2] = make_float2(v.z, v.z);
            *(float2*)&w_s[kq * 4 + 3][o * 2] = make_float2(v.w, v.w);
        }
        const float* cb = g_cplx + s * (NPIX * B64);
        for (int f = t; f < 1024; f += 128) {
            int pos = f >> 4, bq = f & 15;
            int di = pos >> 3, dj = pos & 7;
            float4 v = *(const float4*)&cb[(base_pix + di * DIMS + dj) * B64 + bq * 4];
            *(float4*)&p_s[pos][bq * 4] = v;
        }
        __syncthreads();

#pragma unroll
        for (int k = 0; k < 64; k++) {
            ulonglong2 pv = *(const ulonglong2*)&p_s[k][b0];
            ull wv0 = *(const ull*)&w_s[k][o0 * 2];
            ull wv1 = *(const ull*)&w_s[k][(o0 + 1) * 2];
            fma_x2(acc[0][0], pv.x, wv0);
            fma_x2(acc[0][1], pv.x, wv1);
            fma_x2(acc[1][0], pv.y, wv0);
            fma_x2(acc[1][1], pv.y, wv1);
        }
    }

#pragma unroll
    for (int bp = 0; bp < 2; bp++)
#pragma unroll
        for (int oi = 0; oi < 2; oi++) {
            float2 f = *reinterpret_cast<float2*>(&acc[bp][oi]);
            int o = o0 + oi;
            g_v4[(b0 + bp * 2 + 0) * FLATN + o * V4PIX + p] = f.x;
            g_v4[(b0 + bp * 2 + 1) * FLATN + o * V4PIX + p] = f.y;
        }
}

// ---------------------------------------------------------------------------
// Decision readout: deterministic tree reduction per batch element.
// ---------------------------------------------------------------------------
__global__ __launch_bounds__(256)
void dec_kernel(const float* __restrict__ dw, const float* __restrict__ db,
                float* __restrict__ out)
{
    int b = blockIdx.x;
    int t = threadIdx.x;
    const float* v = g_v4 + b * FLATN;

    float a0 = 0.f, a1 = 0.f;
    for (int idx = t; idx < FLATN; idx += 256) {
        float vv = v[idx];
        a0 += vv * dw[idx];
        a1 += vv * dw[FLATN + idx];
    }

    __shared__ float s0[256], s1[256];
    s0[t] = a0; s1[t] = a1;
    __syncthreads();
    for (int off = 128; off > 0; off >>= 1) {
        if (t < off) { s0[t] += s0[t + off]; s1[t] += s1[t + off]; }
        __syncthreads();
    }
    if (t == 0) {
        out[b * 2 + 0] = s0[0] + db[0];
        out[b * 2 + 1] = s1[0] + db[1];
    }
}

// ---------------------------------------------------------------------------
extern "C" void kernel_launch(void* const* d_in, const int* in_sizes, int n_in,
                              void* d_out, int out_size)
{
    const float* x  = (const float*)d_in[0];   // [64,1,128,128]
    const float* sw = (const float*)d_in[1];   // [32,120,120,81]
    const float* vw = (const float*)d_in[2];   // [16,8,29,29,64]
    const float* dw = (const float*)d_in[3];   // [2,13456]
    const float* db = (const float*)d_in[4];   // [2]
    float* out = (float*)d_out;                // [64,2]

    cudaFuncSetAttribute(v1_kernel, cudaFuncAttributeMaxDynamicSharedMemorySize,
                         SMEM_FLOATS * 4);

    v1_kernel<<<NPIX / (2 * PAIRS), 128, SMEM_FLOATS * 4>>>(x, sw);
    v4_kernel<<<V4PIX, 128>>>(vw);
    dec_kernel<<<B64, 256>>>(dw, db, out);
}